// round 1
// baseline (speedup 1.0000x reference)
#include <cuda_runtime.h>
#include <math.h>

// Problem constants
#define B_   4
#define Q_   75
#define WAY  5
#define SHOT 5
#define HW_  100
#define D_   640
#define NK   5
#define SHW  (SHOT*HW_)   // 500

// GEMM tiling
#define BM   128
#define BNT  128
#define BK   16
#define ASTR 132          // smem stride for As/Bs (k-major, padded)
#define CSTR 129          // smem stride for C tile (conflict-free row scan)

// -------- scratch (__device__ globals; no allocation allowed) --------
__device__ __align__(16) float g_qinv [B_*Q_*HW_];        // 30000
__device__ __align__(16) float g_sinv [B_*WAY*SHOT*HW_];  // 10000
__device__ __align__(16) float g_qmean[B_*Q_*D_];         // 192000
__device__ __align__(16) float g_proto[B_*WAY*D_];        // 12800
__device__ __align__(16) float g_cos  [B_*Q_*WAY];        // 1500
__device__ __align__(16) float g_sim  [B_*Q_*WAY];        // 1500

// ---------------- reciprocal L2 norms, one warp per 640-row ----------------
__global__ void rownorm_kernel(const float* __restrict__ x, int nrows, int which) {
    int gw   = (blockIdx.x * blockDim.x + threadIdx.x) >> 5;
    int lane = threadIdx.x & 31;
    if (gw >= nrows) return;
    const float4* row = reinterpret_cast<const float4*>(x + (size_t)gw * D_);
    float s = 0.f;
#pragma unroll
    for (int i = 0; i < 5; i++) {           // 160 float4 per row, 5 per lane
        float4 v = row[lane + i * 32];
        s += v.x*v.x + v.y*v.y + v.z*v.z + v.w*v.w;
    }
#pragma unroll
    for (int o = 16; o; o >>= 1) s += __shfl_xor_sync(0xffffffffu, s, o);
    if (lane == 0) (which ? g_sinv : g_qinv)[gw] = rsqrtf(s);
}

// ---------------- query_mean[b,q,d] = mean_h qn ----------------
__global__ void qmean_kernel(const float* __restrict__ xq) {
    int bq = blockIdx.x;                    // 0..299
    __shared__ float inv_s[HW_];
    if (threadIdx.x < HW_) inv_s[threadIdx.x] = g_qinv[bq * HW_ + threadIdx.x];
    __syncthreads();
    int d = threadIdx.x;                    // 640 threads
    const float* base = xq + (size_t)bq * HW_ * D_ + d;
    float s = 0.f;
#pragma unroll 4
    for (int h = 0; h < HW_; h++) s += base[(size_t)h * D_] * inv_s[h];
    g_qmean[(size_t)bq * D_ + d] = s * (1.0f / HW_);
}

// ---------------- proto[b,w,d] = mean over shot*HW of sn ----------------
__global__ void proto_kernel(const float* __restrict__ xs) {
    int bw = blockIdx.x;                    // 0..19
    __shared__ float inv_s[SHW];
    for (int i = threadIdx.x; i < SHW; i += blockDim.x)
        inv_s[i] = g_sinv[bw * SHW + i];
    __syncthreads();
    int d = threadIdx.x;                    // 640 threads
    const float* base = xs + (size_t)bw * SHW * D_ + d;
    float s = 0.f;
#pragma unroll 4
    for (int r = 0; r < SHW; r++) s += base[(size_t)r * D_] * inv_s[r];
    g_proto[(size_t)bw * D_ + d] = s * (1.0f / SHW);
}

// ---------------- logits_cos[b,q,w] = qmean . proto ----------------
__global__ void cos_kernel() {
    int blk = blockIdx.x;                   // (b*Q+q)*WAY + w
    int w  = blk % WAY;
    int bq = blk / WAY;
    int b  = bq / Q_;
    const float4* qm = reinterpret_cast<const float4*>(g_qmean + (size_t)bq * D_);
    const float4* pr = reinterpret_cast<const float4*>(g_proto + (size_t)(b*WAY + w) * D_);
    int lane = threadIdx.x;                 // 32 threads
    float s = 0.f;
#pragma unroll
    for (int i = 0; i < 5; i++) {
        float4 a = qm[lane + i * 32];
        float4 c = pr[lane + i * 32];
        s += a.x*c.x + a.y*c.y + a.z*c.z + a.w*c.w;
    }
#pragma unroll
    for (int o = 16; o; o >>= 1) s += __shfl_xor_sync(0xffffffffu, s, o);
    if (lane == 0) g_cos[blk] = s;
}

// ---------------- fused GEMM (100x500x640) + running top-5 + mean ----------------
// block = (b, q, w); 256 threads; thread (tx,ty) in 16x16 computes 8x8 micro-tile
__global__ __launch_bounds__(256, 2)
void fused_dn4_kernel(const float* __restrict__ xq, const float* __restrict__ xs) {
    extern __shared__ float sm[];
    float* As     = sm;                         // BK*ASTR
    float* Bs     = As + BK * ASTR;             // BK*ASTR
    float* Cs     = Bs + BK * ASTR;             // 128*CSTR
    float* qinv_s = Cs + 128 * CSTR;            // 128 (100 used)
    float* sinv_s = qinv_s + 128;               // 512 (500 used)

    int blk = blockIdx.x;
    int w   = blk % WAY;
    int bq  = blk / WAY;
    int b   = bq / Q_;
    const float* A  = xq + (size_t)bq * HW_ * D_;             // [100][640]
    const float* Bp = xs + (size_t)(b*WAY + w) * SHW * D_;    // [500][640]

    int tid = threadIdx.x;
    for (int i = tid; i < HW_; i += 256) qinv_s[i] = g_qinv[bq * HW_ + i];
    for (int i = tid; i < SHW; i += 256) sinv_s[i] = g_sinv[(b*WAY + w) * SHW + i];
    __syncthreads();

    int tx = tid & 15, ty = tid >> 4;

    float t0 = -1e30f, t1 = -1e30f, t2 = -1e30f, t3 = -1e30f, t4 = -1e30f;

    for (int nt = 0; nt < 4; nt++) {
        float acc[8][8];
#pragma unroll
        for (int i = 0; i < 8; i++)
#pragma unroll
            for (int j = 0; j < 8; j++) acc[i][j] = 0.f;

        for (int kt = 0; kt < D_ / BK; kt++) {
            // ---- stage global -> regs (2 float4 for A, 2 for B per thread) ----
            float4 av[2], bv[2];
            int am[2], ak[2];
#pragma unroll
            for (int li = 0; li < 2; li++) {
                int L  = tid + li * 256;      // 0..511 (float4 units)
                int m  = L >> 2;              // row 0..127
                int kq = (L & 3) << 2;        // k sub-offset 0,4,8,12
                am[li] = m; ak[li] = kq;
                if (m < HW_) {
                    float4 v = *reinterpret_cast<const float4*>(A + (size_t)m * D_ + kt * BK + kq);
                    float sc = qinv_s[m];
                    av[li] = make_float4(v.x*sc, v.y*sc, v.z*sc, v.w*sc);
                } else av[li] = make_float4(0.f, 0.f, 0.f, 0.f);
                int ng = nt * BNT + m;
                if (ng < SHW) {
                    float4 v = *reinterpret_cast<const float4*>(Bp + (size_t)ng * D_ + kt * BK + kq);
                    float sc = sinv_s[ng];
                    bv[li] = make_float4(v.x*sc, v.y*sc, v.z*sc, v.w*sc);
                } else bv[li] = make_float4(0.f, 0.f, 0.f, 0.f);
            }
            __syncthreads();   // previous compute finished reading smem
#pragma unroll
            for (int li = 0; li < 2; li++) {
                int m = am[li], kq = ak[li];
                As[(kq+0)*ASTR + m] = av[li].x;
                As[(kq+1)*ASTR + m] = av[li].y;
                As[(kq+2)*ASTR + m] = av[li].z;
                As[(kq+3)*ASTR + m] = av[li].w;
                Bs[(kq+0)*ASTR + m] = bv[li].x;
                Bs[(kq+1)*ASTR + m] = bv[li].y;
                Bs[(kq+2)*ASTR + m] = bv[li].z;
                Bs[(kq+3)*ASTR + m] = bv[li].w;
            }
            __syncthreads();
            // ---- compute ----
#pragma unroll
            for (int k = 0; k < BK; k++) {
                float a[8], bb[8];
                *reinterpret_cast<float4*>(a)    = *reinterpret_cast<const float4*>(As + k*ASTR + ty*8);
                *reinterpret_cast<float4*>(a+4)  = *reinterpret_cast<const float4*>(As + k*ASTR + ty*8 + 4);
                *reinterpret_cast<float4*>(bb)   = *reinterpret_cast<const float4*>(Bs + k*ASTR + tx*8);
                *reinterpret_cast<float4*>(bb+4) = *reinterpret_cast<const float4*>(Bs + k*ASTR + tx*8 + 4);
#pragma unroll
                for (int i = 0; i < 8; i++)
#pragma unroll
                    for (int j = 0; j < 8; j++)
                        acc[i][j] += a[i] * bb[j];
            }
        }
        // ---- stage C tile to smem ----
        __syncthreads();
#pragma unroll
        for (int i = 0; i < 8; i++)
#pragma unroll
            for (int j = 0; j < 8; j++)
                Cs[(ty*8 + i) * CSTR + tx*8 + j] = acc[i][j];
        __syncthreads();
        // ---- merge this tile's columns into running top-5 (one thread per query row) ----
        if (tid < HW_) {
            const float* row = Cs + tid * CSTR;
            int nvalid = SHW - nt * BNT; if (nvalid > BNT) nvalid = BNT;  // 128,128,128,116
            for (int c = 0; c < nvalid; c++) {
                float v = row[c];
                if (v > t4) {
                    if (v > t3) { t4 = t3;
                        if (v > t2) { t3 = t2;
                            if (v > t1) { t2 = t1;
                                if (v > t0) { t1 = t0; t0 = v; } else t1 = v;
                            } else t2 = v;
                        } else t3 = v;
                    } else t4 = v;
                }
            }
        }
        __syncthreads();
    }
    // ---- reduce mean over k and rows ----
    if (tid < HW_) Cs[tid] = t0 + t1 + t2 + t3 + t4;
    __syncthreads();
    if (tid == 0) {
        float s = 0.f;
        for (int i = 0; i < HW_; i++) s += Cs[i];
        g_sim[blk] = s * (1.0f / (HW_ * NK));
    }
}

// ---------------- BatchNorm (batch stats over q) + dilated conv ----------------
__global__ void bnconv_kernel(const float* __restrict__ gamma,
                              const float* __restrict__ beta,
                              const float* __restrict__ convw,
                              float* __restrict__ out) {
    __shared__ float mu_s[B_*2*WAY], istd_s[B_*2*WAY];
    int t = threadIdx.x;
    if (t < B_*2*WAY) {                     // 40 (b,channel) pairs
        int b = t / (2*WAY), c = t % (2*WAY);
        const float* src = (c < WAY) ? g_cos : g_sim;
        int ch = (c < WAY) ? c : c - WAY;
        float s = 0.f, s2 = 0.f;
        for (int q = 0; q < Q_; q++) {
            float v = src[(b*Q_ + q) * WAY + ch];
            s += v; s2 += v * v;
        }
        float m   = s  * (1.0f / Q_);
        float var = s2 * (1.0f / Q_) - m * m;   // biased, as torch BN
        mu_s[t]   = m;
        istd_s[t] = rsqrtf(var + 1e-5f);
    }
    __syncthreads();
    float w0 = convw[0], w1 = convw[1];
    for (int idx = t; idx < B_*Q_*WAY; idx += blockDim.x) {
        int j   = idx % WAY;
        int bq  = idx / WAY;
        int b   = bq / Q_;
        int c0  = j;          // cos channel
        int c1  = j + WAY;    // sim channel
        float f0 = g_cos[bq * WAY + j];
        float f1 = g_sim[bq * WAY + j];
        float bn0 = (f0 - mu_s[b*2*WAY + c0]) * istd_s[b*2*WAY + c0] * gamma[c0] + beta[c0];
        float bn1 = (f1 - mu_s[b*2*WAY + c1]) * istd_s[b*2*WAY + c1] * gamma[c1] + beta[c1];
        out[idx] = w0 * bn0 + w1 * bn1;
    }
}

// ---------------- launch ----------------
extern "C" void kernel_launch(void* const* d_in, const int* in_sizes, int n_in,
                              void* d_out, int out_size) {
    const float* xq    = (const float*)d_in[0];  // [4,75,100,640]
    const float* xs    = (const float*)d_in[1];  // [4,5,5,100,640]
    const float* gamma = (const float*)d_in[2];  // [10]
    const float* beta  = (const float*)d_in[3];  // [10]
    const float* convw = (const float*)d_in[4];  // [2]
    float* out = (float*)d_out;                  // [4,75,5]

    const int smem_bytes = (2 * BK * ASTR + 128 * CSTR + 128 + 512) * (int)sizeof(float); // 85504
    cudaFuncSetAttribute(fused_dn4_kernel,
                         cudaFuncAttributeMaxDynamicSharedMemorySize, smem_bytes);

    int nq_rows = B_*Q_*HW_;        // 30000
    int ns_rows = B_*WAY*SHOT*HW_;  // 10000
    rownorm_kernel<<<(nq_rows*32 + 255)/256, 256>>>(xq, nq_rows, 0);
    rownorm_kernel<<<(ns_rows*32 + 255)/256, 256>>>(xs, ns_rows, 1);
    qmean_kernel<<<B_*Q_, D_>>>(xq);
    proto_kernel<<<B_*WAY, D_>>>(xs);
    cos_kernel<<<B_*Q_*WAY, 32>>>();
    fused_dn4_kernel<<<B_*Q_*WAY, 256, smem_bytes>>>(xq, xs);
    bnconv_kernel<<<1, 256>>>(gamma, beta, convw, out);
}